// round 6
// baseline (speedup 1.0000x reference)
#include <cuda_runtime.h>

#define Bb 64
#define Nn 1000
#define FUTc 12
#define Oo 16
#define Hh 128
#define Ee 64
#define Gg 512
#define TSTEPS (Nn * FUTc)

typedef unsigned long long u64;

// Scratch (allocation-free rule: __device__ globals)
__device__ float g_encacc[(size_t)Bb * Nn * Gg];   // per (b,n): enc part of cell0 gates + bias
__device__ float g_nm[Bb * Nn * Oo];               // node means

// ---------- packed fp32x2 helpers ----------
__device__ __forceinline__ void ffma2(u64 &acc, u64 a, u64 b) {
    asm("fma.rn.f32x2 %0, %1, %2, %0;" : "+l"(acc) : "l"(a), "l"(b));
}
__device__ __forceinline__ u64 add2(u64 a, u64 b) {
    u64 r; asm("add.rn.f32x2 %0, %1, %2;" : "=l"(r) : "l"(a), "l"(b)); return r;
}
__device__ __forceinline__ u64 pack2(float x, float y) {
    u64 r; asm("mov.b64 %0, {%1, %2};" : "=l"(r) : "f"(x), "f"(y)); return r;
}
__device__ __forceinline__ void unpack2(u64 v, float &x, float &y) {
    asm("mov.b64 {%0, %1}, %2;" : "=f"(x), "=f"(y) : "l"(v));
}

// ---------- MUFU activations ----------
__device__ __forceinline__ float tanhfast(float x) {
    float r; asm("tanh.approx.f32 %0, %1;" : "=f"(r) : "f"(x)); return r;
}
__device__ __forceinline__ float sigm(float x) {
    return fmaf(0.5f, tanhfast(0.5f * x), 0.5f);
}

// ---------- shared-memory release/acquire flag ops ----------
__device__ __forceinline__ unsigned ldacq(const unsigned* p) {
    unsigned v;
    unsigned a = (unsigned)__cvta_generic_to_shared((void*)p);
    asm volatile("ld.acquire.cta.shared.u32 %0, [%1];" : "=r"(v) : "r"(a));
    return v;
}
__device__ __forceinline__ void redrel(unsigned* p) {
    unsigned a = (unsigned)__cvta_generic_to_shared((void*)p);
    asm volatile("red.release.cta.shared.add.u32 [%0], 1;" :: "r"(a) : "memory");
}
#define POLL_GE(cnt, tgt)  do { } while (ldacq(&(cnt)) < (tgt))

// ---------- precompute: enc part of cell0 gates (tiled, coalesced) ----------
__global__ void __launch_bounds__(256) enc_precompute(const float* __restrict__ enc,
                               const float* __restrict__ Wih0,
                               const float* __restrict__ bih0,
                               const float* __restrict__ bhh0) {
    __shared__ float se[32][64];
    __shared__ float sw[128][65];
    const int t = threadIdx.x;
    const size_t r0 = (size_t)blockIdx.x * 32;

    for (int i = t; i < 32 * 64; i += 256)
        se[i >> 6][i & 63] = enc[r0 * 64 + i];

    const int rq = t >> 5;
    const int gq = t & 31;

    for (int gt = 0; gt < 4; gt++) {
        __syncthreads();
        for (int i = t; i < 128 * 64; i += 256)
            sw[i >> 6][i & 63] = Wih0[(size_t)(gt * 128 + (i >> 6)) * 80 + (i & 63)];
        __syncthreads();

        float acc[4][4];
#pragma unroll
        for (int gi = 0; gi < 4; gi++) {
            const int g = gt * 128 + gq + 32 * gi;
            const float bb = bih0[g] + bhh0[g];
#pragma unroll
            for (int rr = 0; rr < 4; rr++) acc[gi][rr] = bb;
        }
#pragma unroll 4
        for (int e = 0; e < 64; e++) {
            const float w0 = sw[gq][e], w1 = sw[gq + 32][e];
            const float w2 = sw[gq + 64][e], w3 = sw[gq + 96][e];
#pragma unroll
            for (int rr = 0; rr < 4; rr++) {
                const float x = se[rq * 4 + rr][e];
                acc[0][rr] += x * w0; acc[1][rr] += x * w1;
                acc[2][rr] += x * w2; acc[3][rr] += x * w3;
            }
        }
#pragma unroll
        for (int gi = 0; gi < 4; gi++)
#pragma unroll
            for (int rr = 0; rr < 4; rr++)
                g_encacc[(r0 + rq * 4 + rr) * Gg + gt * 128 + gq + 32 * gi] = acc[gi][rr];
    }
}

// ---------- precompute: node means ----------
__global__ void nm_precompute(const float* __restrict__ mean) {
    const int idx = blockIdx.x * 256 + threadIdx.x;
    if (idx >= Bb * Nn * Oo) return;
    const int o = idx & 15;
    const int rem = idx >> 4;
    const int n = rem % Nn;
    const int b = rem / Nn;
    float acc = 0.f;
#pragma unroll
    for (int f = 0; f < FUTc; f++)
        acc += mean[((size_t)(b * FUTc + f) * Nn + n) * Oo + o];
    g_nm[idx] = acc * (1.f / 12.f);
}

// ---------- main recurrent kernel: 1 batch chain per CTA ----------
__global__ void __launch_bounds__(256, 1)
decoder_main(const float* __restrict__ s0v, const float* __restrict__ h0v,
             const float* __restrict__ c0v,
             const float* __restrict__ Wih0, const float* __restrict__ Whh0,
             const float* __restrict__ Whr0,
             const float* __restrict__ Wih1, const float* __restrict__ Whh1,
             const float* __restrict__ bih1, const float* __restrict__ bhh1,
             const float* __restrict__ Whr1,
             float* __restrict__ out) {
    __shared__ u64 s_x0[32];       // [0:16)=loop  [16:32)=h1
    __shared__ u64 s_x1[32];       // [0:16)=h1'   [16:32)=h2
    __shared__ u64 s_hfp[64];      // cell0 h_full as float pairs
    __shared__ u64 s_hf2p[64];     // cell1 h_full as float pairs
    __shared__ unsigned cE1, cE3, cE4, cE5;   // monotonic edge counters

    float* s_hf  = (float*)s_hfp;
    float* s_hf2 = (float*)s_hf2p;

    const int t = threadIdx.x;
    const int j = t & 127;
    const bool role0 = (t < 128);
    const int warp = t >> 5;
    const int lane = t & 31;
    const int grp = lane >> 3;     // 8-lane reduction group (0..3)
    const int sub = lane & 7;
    const int b = blockIdx.x;

    // ---- persistent register weights ----
    u64 wIF[32], wGO[32];
    u64 whrp[8];                   // Whr row slice as input pairs
    float cst;
    u64 encIF = 0, encGO = 0;      // role0: enc+bias seed for current node
    u64 cIF = 0, cGO = 0;          // role0: carried h1-half of next gates
    u64 aIF = 0, aGO = 0;          // role1: A->C carried partial gates
    u64 bIF = 0, bGO = 0;          // role1 bias
    float nm_cur = 0.f, nm_nxt = 0.f;
    float pf0 = 0.f, pf1 = 0.f, pf2 = 0.f, pf3 = 0.f;

    const int o_r0 = 4 * warp + grp;         // role0 projection output
    const int o_r1 = 4 * (warp - 4) + grp;   // role1 projection output

    if (t == 0) { cE1 = 0; cE3 = 0; cE4 = 0; cE5 = 0; }

    if (role0) {
#pragma unroll
        for (int k = 0; k < 16; k++) {
            wIF[k]      = pack2(Wih0[j * 80 + 64 + k],         Wih0[(128 + j) * 80 + 64 + k]);
            wGO[k]      = pack2(Wih0[(256 + j) * 80 + 64 + k], Wih0[(384 + j) * 80 + 64 + k]);
            wIF[16 + k] = pack2(Whh0[j * 16 + k],              Whh0[(128 + j) * 16 + k]);
            wGO[16 + k] = pack2(Whh0[(256 + j) * 16 + k],      Whh0[(384 + j) * 16 + k]);
        }
#pragma unroll
        for (int m = 0; m < 8; m++)
            whrp[m] = pack2(Whr0[o_r0 * 128 + 2 * (sub + 8 * m)],
                            Whr0[o_r0 * 128 + 2 * (sub + 8 * m) + 1]);
        cst = c0v[j];
        const float* ea = g_encacc + ((size_t)b * Nn + 0) * Gg;
        encIF = pack2(ea[j], ea[128 + j]);
        encGO = pack2(ea[256 + j], ea[384 + j]);
    } else {
#pragma unroll
        for (int k = 0; k < 16; k++) {
            wIF[k]      = pack2(Wih1[j * 16 + k],         Wih1[(128 + j) * 16 + k]);
            wGO[k]      = pack2(Wih1[(256 + j) * 16 + k], Wih1[(384 + j) * 16 + k]);
            wIF[16 + k] = pack2(Whh1[j * 16 + k],         Whh1[(128 + j) * 16 + k]);
            wGO[16 + k] = pack2(Whh1[(256 + j) * 16 + k], Whh1[(384 + j) * 16 + k]);
        }
#pragma unroll
        for (int m = 0; m < 8; m++)
            whrp[m] = pack2(Whr1[o_r1 * 128 + 2 * (sub + 8 * m)],
                            Whr1[o_r1 * 128 + 2 * (sub + 8 * m) + 1]);
        bIF = pack2(bih1[j] + bhh1[j],             bih1[128 + j] + bhh1[128 + j]);
        bGO = pack2(bih1[256 + j] + bhh1[256 + j], bih1[384 + j] + bhh1[384 + j]);
        cst = c0v[128 + j];
        if (sub == 0) {
            nm_cur = g_nm[((size_t)b * Nn + 0) * Oo + o_r1];
            const float lp = s0v[o_r1] + nm_cur;
            s_x0[o_r1] = pack2(lp, lp);
            const float h1i = h0v[o_r1];      s_x0[16 + o_r1] = pack2(h1i, h1i);
            const float h2i = h0v[16 + o_r1]; s_x1[16 + o_r1] = pack2(h2i, h2i);
        }
    }
    __syncthreads();

    // prologue: role0 initial carried h1-half (from h0)
    if (role0) {
        u64 a0 = 0, a1 = 0, g0 = 0, g1 = 0;
#pragma unroll
        for (int k = 16; k < 32; k += 2) {
            const u64 xe = s_x0[k], xo = s_x0[k + 1];
            ffma2(a0, xe, wIF[k]); ffma2(a1, xo, wIF[k + 1]);
            ffma2(g0, xe, wGO[k]); ffma2(g1, xo, wGO[k + 1]);
        }
        cIF = add2(a0, a1); cGO = add2(g0, g1);
    }
    __syncthreads();

    int n = 0, rep = 0;
    unsigned base = 0;   // 4*step

#pragma unroll 1
    for (int step = 0; step < TSTEPS; step++) {
        const unsigned tgt = base + 4;
        if (role0) {
            POLL_GE(cE4, base);                      // prev-step state published

            // ---- Phase A: finish cell0 gates (enc seed + carried h1 + W.loop) ----
            u64 a0 = encIF, a1 = cIF, g0 = encGO, g1 = cGO;
#pragma unroll
            for (int k = 0; k < 16; k += 2) {
                const u64 xe = s_x0[k], xo = s_x0[k + 1];
                ffma2(a0, xe, wIF[k]); ffma2(a1, xo, wIF[k + 1]);
                ffma2(g0, xe, wGO[k]); ffma2(g1, xo, wGO[k + 1]);
            }
            const u64 tIF = add2(a0, a1), tGO = add2(g0, g1);
            float gi_, gf_, gg_, go_;
            unpack2(tIF, gi_, gf_);
            unpack2(tGO, gg_, go_);
            const float iv = sigm(gi_), fv = sigm(gf_), gv = tanhfast(gg_), ov = sigm(go_);
            cst = fv * cst + iv * gv;
            s_hf[j] = ov * tanhfast(cst);

            __syncwarp();
            if (lane == 0) redrel(&cE1);             // publish hf within role0
            POLL_GE(cE1, tgt);

            // ---- Phase B: hr0 projection (8-lane groups, f32x2, conflict-free) ----
            {
                u64 q0 = 0, q1 = 0;
#pragma unroll
                for (int m = 0; m < 8; m += 2) {
                    ffma2(q0, s_hfp[sub + 8 * m],       whrp[m]);
                    ffma2(q1, s_hfp[sub + 8 * (m + 1)], whrp[m + 1]);
                }
                const u64 qt = add2(q0, q1);
                float qa, qb; unpack2(qt, qa, qb);
                float pr = qa + qb;
                pr += __shfl_xor_sync(0xffffffffu, pr, 1);
                pr += __shfl_xor_sync(0xffffffffu, pr, 2);
                pr += __shfl_xor_sync(0xffffffffu, pr, 4);
                if (sub == 0) {
                    s_x1[o_r0]      = pack2(pr, pr);   // h1' for cell1 (this step)
                    s_x0[16 + o_r0] = pack2(pr, pr);   // h1 for cell0 (next step)
                }
            }
            __syncwarp();
            if (lane == 0) redrel(&cE3);             // publish h1'
            POLL_GE(cE3, tgt);                        // (immediate) h1 visible for C

            // ---- Phase C: carried h1-half for NEXT step ----
            {
                u64 c0_ = 0, c1_ = 0, d0 = 0, d1 = 0;
#pragma unroll
                for (int k = 16; k < 32; k += 2) {
                    const u64 xe = s_x0[k], xo = s_x0[k + 1];
                    ffma2(c0_, xe, wIF[k]); ffma2(c1_, xo, wIF[k + 1]);
                    ffma2(d0, xe, wGO[k]); ffma2(d1, xo, wGO[k + 1]);
                }
                cIF = add2(c0_, c1_); cGO = add2(d0, d1);
            }
            // node-boundary enc prefetch / consume (registers only)
            if (rep == 8 && n + 1 < Nn) {
                const float* ea = g_encacc + ((size_t)b * Nn + (n + 1)) * Gg;
                pf0 = ea[j]; pf1 = ea[128 + j]; pf2 = ea[256 + j]; pf3 = ea[384 + j];
            }
            if (rep == 11 && n + 1 < Nn) {
                encIF = pack2(pf0, pf1);
                encGO = pack2(pf2, pf3);
            }
        } else {
            POLL_GE(cE4, base);                      // prev-step h2 published

            // ---- Phase A': cell1 gates, h2-dependent half ----
            u64 a0 = bIF, a1 = 0, g0 = bGO, g1 = 0;
#pragma unroll
            for (int k = 16; k < 32; k += 2) {
                const u64 xe = s_x1[k], xo = s_x1[k + 1];
                ffma2(a0, xe, wIF[k]); ffma2(a1, xo, wIF[k + 1]);
                ffma2(g0, xe, wGO[k]); ffma2(g1, xo, wGO[k + 1]);
            }
            aIF = add2(a0, a1); aGO = add2(g0, g1);

            POLL_GE(cE3, tgt);                        // wait h1' from role0

            // ---- Phase C': finish cell1 gates + activations ----
            {
                u64 c0_ = aIF, c1_ = 0, d0 = aGO, d1 = 0;
#pragma unroll
                for (int k = 0; k < 16; k += 2) {
                    const u64 xe = s_x1[k], xo = s_x1[k + 1];
                    ffma2(c0_, xe, wIF[k]); ffma2(c1_, xo, wIF[k + 1]);
                    ffma2(d0, xe, wGO[k]); ffma2(d1, xo, wGO[k + 1]);
                }
                const u64 tIF = add2(c0_, c1_), tGO = add2(d0, d1);
                float gi_, gf_, gg_, go_;
                unpack2(tIF, gi_, gf_);
                unpack2(tGO, gg_, go_);
                const float iv = sigm(gi_), fv = sigm(gf_), gv = tanhfast(gg_), ov = sigm(go_);
                cst = fv * cst + iv * gv;
                s_hf2[j] = ov * tanhfast(cst);
            }
            __syncwarp();
            if (lane == 0) redrel(&cE5);             // publish hf2 within role1
            POLL_GE(cE5, tgt);

            // ---- Phase D: hr1 + next-step state + output ----
            {
                u64 q0 = 0, q1 = 0;
#pragma unroll
                for (int m = 0; m < 8; m += 2) {
                    ffma2(q0, s_hf2p[sub + 8 * m],       whrp[m]);
                    ffma2(q1, s_hf2p[sub + 8 * (m + 1)], whrp[m + 1]);
                }
                const u64 qt = add2(q0, q1);
                float qa, qb; unpack2(qt, qa, qb);
                float pr = qa + qb;
                pr += __shfl_xor_sync(0xffffffffu, pr, 1);
                pr += __shfl_xor_sync(0xffffffffu, pr, 2);
                pr += __shfl_xor_sync(0xffffffffu, pr, 4);
                float v = 0.f;
                if (sub == 0) {
                    v = pr;   // h2_new
                    const float lp = v + ((rep == 11) ? nm_nxt : nm_cur);
                    s_x0[o_r1]      = pack2(lp, lp);
                    s_x1[16 + o_r1] = pack2(v, v);
                }
                __syncwarp();
                if (lane == 0) redrel(&cE4);         // publish state to role0
                if (sub == 0)
                    out[(((size_t)b * FUTc + rep) * Nn + n) * Oo + o_r1] = v + nm_cur;
            }

            if (sub == 0) {
                if (rep == 8 && n + 1 < Nn)
                    nm_nxt = g_nm[((size_t)b * Nn + (n + 1)) * Oo + o_r1];
                if (rep == 11) nm_cur = nm_nxt;
            }
        }

        base += 4;
        rep++;
        if (rep == FUTc) { rep = 0; n++; }
    }
}

extern "C" void kernel_launch(void* const* d_in, const int* in_sizes, int n_in,
                              void* d_out, int out_size) {
    const float* enc  = (const float*)d_in[0];
    const float* mean = (const float*)d_in[1];
    const float* s    = (const float*)d_in[2];
    const float* h0   = (const float*)d_in[3];
    const float* c0   = (const float*)d_in[4];
    const float* Wih0 = (const float*)d_in[5];
    const float* Whh0 = (const float*)d_in[6];
    const float* bih0 = (const float*)d_in[7];
    const float* bhh0 = (const float*)d_in[8];
    const float* Whr0 = (const float*)d_in[9];
    const float* Wih1 = (const float*)d_in[10];
    const float* Whh1 = (const float*)d_in[11];
    const float* bih1 = (const float*)d_in[12];
    const float* bhh1 = (const float*)d_in[13];
    const float* Whr1 = (const float*)d_in[14];
    float* out = (float*)d_out;

    enc_precompute<<<(Bb * Nn) / 32, 256>>>(enc, Wih0, bih0, bhh0);
    nm_precompute<<<(Bb * Nn * Oo + 255) / 256, 256>>>(mean);
    decoder_main<<<Bb, 256>>>(s, h0, c0, Wih0, Whh0, Whr0,
                              Wih1, Whh1, bih1, bhh1, Whr1, out);
}

// round 7
// speedup vs baseline: 1.6788x; 1.6788x over previous
#include <cuda_runtime.h>

#define Bb 64
#define Nn 1000
#define FUTc 12
#define Oo 16
#define Hh 128
#define Ee 64
#define Gg 512

typedef unsigned long long u64;

// Scratch (allocation-free rule: __device__ globals)
__device__ float g_encacc[(size_t)Bb * Nn * Gg];   // per (b,n): enc part of cell0 gates + bias (i/f/o rows pre-scaled 0.5)
__device__ float g_nm[Bb * Nn * Oo];               // node means

// ---------- packed fp32x2 helpers ----------
__device__ __forceinline__ void ffma2(u64 &acc, u64 a, u64 b) {
    asm("fma.rn.f32x2 %0, %1, %2, %0;" : "+l"(acc) : "l"(a), "l"(b));
}
__device__ __forceinline__ u64 add2(u64 a, u64 b) {
    u64 r; asm("add.rn.f32x2 %0, %1, %2;" : "=l"(r) : "l"(a), "l"(b)); return r;
}
__device__ __forceinline__ u64 pack2(float x, float y) {
    u64 r; asm("mov.b64 %0, {%1, %2};" : "=l"(r) : "f"(x), "f"(y)); return r;
}
__device__ __forceinline__ void unpack2(u64 v, float &x, float &y) {
    asm("mov.b64 {%0, %1}, %2;" : "=f"(x), "=f"(y) : "l"(v));
}

// ---------- MUFU activations (gate pre-scaled by 0.5 for sigmoids) ----------
__device__ __forceinline__ float tanhfast(float x) {
    float r; asm("tanh.approx.f32 %0, %1;" : "=f"(r) : "f"(x)); return r;
}

// ---------- precompute: enc part of cell0 gates (tiled, coalesced) ----------
__global__ void __launch_bounds__(256) enc_precompute(const float* __restrict__ enc,
                               const float* __restrict__ Wih0,
                               const float* __restrict__ bih0,
                               const float* __restrict__ bhh0) {
    __shared__ float se[32][64];
    __shared__ float sw[128][65];
    const int t = threadIdx.x;
    const size_t r0 = (size_t)blockIdx.x * 32;

    for (int i = t; i < 32 * 64; i += 256)
        se[i >> 6][i & 63] = enc[r0 * 64 + i];

    const int rq = t >> 5;
    const int gq = t & 31;

    for (int gt = 0; gt < 4; gt++) {
        const float sc = (gt == 2) ? 1.0f : 0.5f;   // i,f,o rows pre-scaled
        __syncthreads();
        for (int i = t; i < 128 * 64; i += 256)
            sw[i >> 6][i & 63] = Wih0[(size_t)(gt * 128 + (i >> 6)) * 80 + (i & 63)];
        __syncthreads();

        float acc[4][4];
#pragma unroll
        for (int gi = 0; gi < 4; gi++) {
            const int g = gt * 128 + gq + 32 * gi;
            const float bb = bih0[g] + bhh0[g];
#pragma unroll
            for (int rr = 0; rr < 4; rr++) acc[gi][rr] = bb;
        }
#pragma unroll 4
        for (int e = 0; e < 64; e++) {
            const float w0 = sw[gq][e], w1 = sw[gq + 32][e];
            const float w2 = sw[gq + 64][e], w3 = sw[gq + 96][e];
#pragma unroll
            for (int rr = 0; rr < 4; rr++) {
                const float x = se[rq * 4 + rr][e];
                acc[0][rr] += x * w0; acc[1][rr] += x * w1;
                acc[2][rr] += x * w2; acc[3][rr] += x * w3;
            }
        }
#pragma unroll
        for (int gi = 0; gi < 4; gi++)
#pragma unroll
            for (int rr = 0; rr < 4; rr++)
                g_encacc[(r0 + rq * 4 + rr) * Gg + gt * 128 + gq + 32 * gi] = sc * acc[gi][rr];
    }
}

// ---------- precompute: node means ----------
__global__ void nm_precompute(const float* __restrict__ mean) {
    const int idx = blockIdx.x * 256 + threadIdx.x;
    if (idx >= Bb * Nn * Oo) return;
    const int o = idx & 15;
    const int rem = idx >> 4;
    const int n = rem % Nn;
    const int b = rem / Nn;
    float acc = 0.f;
#pragma unroll
    for (int f = 0; f < FUTc; f++)
        acc += mean[((size_t)(b * FUTc + f) * Nn + n) * Oo + o];
    g_nm[idx] = acc * (1.f / 12.f);
}

// One decode step. PF: issue next-node prefetch. CONS: consume prefetch / swap nm.
#define STEP_CORE(PF, CONS)                                                          \
{                                                                                    \
    if (role0) {                                                                     \
        asm volatile("bar.sync 4, 256;" ::: "memory");                               \
        u64 a0 = encIF, a1 = cIF, g0 = encGO, g1 = cGO;                              \
        _Pragma("unroll")                                                            \
        for (int k = 0; k < 16; k += 2) {                                            \
            const u64 xe = s_x0[k], xo = s_x0[k + 1];                                \
            ffma2(a0, xe, wIF[k]); ffma2(a1, xo, wIF[k + 1]);                        \
            ffma2(g0, xe, wGO[k]); ffma2(g1, xo, wGO[k + 1]);                        \
        }                                                                            \
        const u64 tIF = add2(a0, a1), tGO = add2(g0, g1);                            \
        float gi_, gf_, gg_, go_;                                                    \
        unpack2(tIF, gi_, gf_); unpack2(tGO, gg_, go_);                              \
        const float iv = fmaf(0.5f, tanhfast(gi_), 0.5f);                            \
        const float fv = fmaf(0.5f, tanhfast(gf_), 0.5f);                            \
        const float gv = tanhfast(gg_);                                              \
        const float ov = fmaf(0.5f, tanhfast(go_), 0.5f);                            \
        cst = fv * cst + iv * gv;                                                    \
        s_hf[j] = ov * tanhfast(cst);                                                \
        asm volatile("bar.sync 1, 128;" ::: "memory");                               \
        {                                                                            \
            u64 q0 = 0, q1 = 0;                                                      \
            _Pragma("unroll")                                                        \
            for (int m = 0; m < 8; m += 2) {                                         \
                ffma2(q0, s_hfp[sub + 8 * m],       whrp[m]);                        \
                ffma2(q1, s_hfp[sub + 8 * (m + 1)], whrp[m + 1]);                    \
            }                                                                        \
            const u64 qt = add2(q0, q1);                                             \
            float qa, qb; unpack2(qt, qa, qb);                                       \
            float pr = qa + qb;                                                      \
            pr += __shfl_xor_sync(0xffffffffu, pr, 1);                               \
            pr += __shfl_xor_sync(0xffffffffu, pr, 2);                               \
            pr += __shfl_xor_sync(0xffffffffu, pr, 4);                               \
            if (sub == 0) {                                                          \
                s_x1[o_r0]      = pack2(pr, pr);                                     \
                s_x0[16 + o_r0] = pack2(pr, pr);                                     \
            }                                                                        \
        }                                                                            \
        asm volatile("bar.arrive 3, 256;" ::: "memory");                             \
        asm volatile("bar.sync 2, 128;" ::: "memory");                               \
        {                                                                            \
            u64 c0_ = 0, c1_ = 0, d0 = 0, d1 = 0;                                    \
            _Pragma("unroll")                                                        \
            for (int k = 16; k < 32; k += 2) {                                       \
                const u64 xe = s_x0[k], xo = s_x0[k + 1];                            \
                ffma2(c0_, xe, wIF[k]); ffma2(c1_, xo, wIF[k + 1]);                  \
                ffma2(d0, xe, wGO[k]); ffma2(d1, xo, wGO[k + 1]);                    \
            }                                                                        \
            cIF = add2(c0_, c1_); cGO = add2(d0, d1);                                \
        }                                                                            \
        if (PF) {                                                                    \
            if (n + 1 < Nn) {                                                        \
                const float* ea = g_encacc + ((size_t)b * Nn + (n + 1)) * Gg;        \
                pf0 = ea[j]; pf1 = ea[128 + j];                                      \
                pf2 = ea[256 + j]; pf3 = ea[384 + j];                                \
            }                                                                        \
        }                                                                            \
        if (CONS) {                                                                  \
            if (n + 1 < Nn) { encIF = pack2(pf0, pf1); encGO = pack2(pf2, pf3); }    \
        }                                                                            \
    } else {                                                                         \
        u64 a0 = bIF, a1 = 0, g0 = bGO, g1 = 0;                                      \
        _Pragma("unroll")                                                            \
        for (int k = 16; k < 32; k += 2) {                                           \
            const u64 xe = s_x1[k], xo = s_x1[k + 1];                                \
            ffma2(a0, xe, wIF[k]); ffma2(a1, xo, wIF[k + 1]);                        \
            ffma2(g0, xe, wGO[k]); ffma2(g1, xo, wGO[k + 1]);                        \
        }                                                                            \
        aIF = add2(a0, a1); aGO = add2(g0, g1);                                      \
        asm volatile("bar.sync 3, 256;" ::: "memory");                               \
        {                                                                            \
            u64 c0_ = aIF, c1_ = 0, d0 = aGO, d1 = 0;                                \
            _Pragma("unroll")                                                        \
            for (int k = 0; k < 16; k += 2) {                                        \
                const u64 xe = s_x1[k], xo = s_x1[k + 1];                            \
                ffma2(c0_, xe, wIF[k]); ffma2(c1_, xo, wIF[k + 1]);                  \
                ffma2(d0, xe, wGO[k]); ffma2(d1, xo, wGO[k + 1]);                    \
            }                                                                        \
            const u64 tIF = add2(c0_, c1_), tGO = add2(d0, d1);                      \
            float gi_, gf_, gg_, go_;                                                \
            unpack2(tIF, gi_, gf_); unpack2(tGO, gg_, go_);                          \
            const float iv = fmaf(0.5f, tanhfast(gi_), 0.5f);                        \
            const float fv = fmaf(0.5f, tanhfast(gf_), 0.5f);                        \
            const float gv = tanhfast(gg_);                                          \
            const float ov = fmaf(0.5f, tanhfast(go_), 0.5f);                        \
            cst = fv * cst + iv * gv;                                                \
            s_hf2[j] = ov * tanhfast(cst);                                           \
        }                                                                            \
        asm volatile("bar.sync 5, 128;" ::: "memory");                               \
        {                                                                            \
            u64 q0 = 0, q1 = 0;                                                      \
            _Pragma("unroll")                                                        \
            for (int m = 0; m < 8; m += 2) {                                         \
                ffma2(q0, s_hf2p[sub + 8 * m],       whrp[m]);                       \
                ffma2(q1, s_hf2p[sub + 8 * (m + 1)], whrp[m + 1]);                   \
            }                                                                        \
            const u64 qt = add2(q0, q1);                                             \
            float qa, qb; unpack2(qt, qa, qb);                                       \
            float pr = qa + qb;                                                      \
            pr += __shfl_xor_sync(0xffffffffu, pr, 1);                               \
            pr += __shfl_xor_sync(0xffffffffu, pr, 2);                               \
            pr += __shfl_xor_sync(0xffffffffu, pr, 4);                               \
            float v = 0.f;                                                           \
            if (sub == 0) {                                                          \
                v = pr;                                                              \
                const float lp = v + ((CONS) ? nm_nxt : nm_cur);                     \
                s_x0[o_r1]      = pack2(lp, lp);                                     \
                s_x1[16 + o_r1] = pack2(v, v);                                       \
            }                                                                        \
            asm volatile("bar.arrive 4, 256;" ::: "memory");                         \
            if (sub == 0) out[optr] = v + nm_cur;                                    \
        }                                                                            \
        asm volatile("bar.sync 6, 128;" ::: "memory");                               \
        if (PF) {                                                                    \
            if (sub == 0 && n + 1 < Nn)                                              \
                nm_nxt = g_nm[((size_t)b * Nn + (n + 1)) * Oo + o_r1];               \
        }                                                                            \
        if (CONS) { if (sub == 0) nm_cur = nm_nxt; }                                 \
        optr += Nn * Oo;                                                             \
    }                                                                                \
}

// ---------- main recurrent kernel: 1 batch chain per CTA ----------
__global__ void __launch_bounds__(256, 1)
decoder_main(const float* __restrict__ s0v, const float* __restrict__ h0v,
             const float* __restrict__ c0v,
             const float* __restrict__ Wih0, const float* __restrict__ Whh0,
             const float* __restrict__ Whr0,
             const float* __restrict__ Wih1, const float* __restrict__ Whh1,
             const float* __restrict__ bih1, const float* __restrict__ bhh1,
             const float* __restrict__ Whr1,
             float* __restrict__ out) {
    __shared__ u64 s_x0[32];       // [0:16)=loop  [16:32)=h1
    __shared__ u64 s_x1[32];       // [0:16)=h1'   [16:32)=h2
    __shared__ u64 s_hfp[64];      // cell0 h_full as float pairs
    __shared__ u64 s_hf2p[64];     // cell1 h_full as float pairs

    float* s_hf  = (float*)s_hfp;
    float* s_hf2 = (float*)s_hf2p;

    const int t = threadIdx.x;
    const int j = t & 127;
    const bool role0 = (t < 128);
    const int warp = t >> 5;
    const int lane = t & 31;
    const int grp = lane >> 3;     // 8-lane reduction group (0..3)
    const int sub = lane & 7;
    const int b = blockIdx.x;

    // ---- persistent register weights (i/f/o components pre-scaled 0.5) ----
    u64 wIF[32], wGO[32];
    u64 whrp[8];                   // Whr row slice as input pairs
    float cst;
    u64 encIF = 0, encGO = 0;      // role0: enc+bias seed for current node
    u64 cIF = 0, cGO = 0;          // role0: carried h1-half of next gates
    u64 aIF = 0, aGO = 0;          // role1: A->C carried partial gates
    u64 bIF = 0, bGO = 0;          // role1 bias
    float nm_cur = 0.f, nm_nxt = 0.f;
    float pf0 = 0.f, pf1 = 0.f, pf2 = 0.f, pf3 = 0.f;
    unsigned optr = 0;

    const int o_r0 = 4 * warp + grp;         // role0 projection output
    const int o_r1 = 4 * (warp - 4) + grp;   // role1 projection output

    if (role0) {
#pragma unroll
        for (int k = 0; k < 16; k++) {
            wIF[k]      = pack2(0.5f * Wih0[j * 80 + 64 + k],  0.5f * Wih0[(128 + j) * 80 + 64 + k]);
            wGO[k]      = pack2(Wih0[(256 + j) * 80 + 64 + k], 0.5f * Wih0[(384 + j) * 80 + 64 + k]);
            wIF[16 + k] = pack2(0.5f * Whh0[j * 16 + k],       0.5f * Whh0[(128 + j) * 16 + k]);
            wGO[16 + k] = pack2(Whh0[(256 + j) * 16 + k],      0.5f * Whh0[(384 + j) * 16 + k]);
        }
#pragma unroll
        for (int m = 0; m < 8; m++)
            whrp[m] = pack2(Whr0[o_r0 * 128 + 2 * (sub + 8 * m)],
                            Whr0[o_r0 * 128 + 2 * (sub + 8 * m) + 1]);
        cst = c0v[j];
        const float* ea = g_encacc + ((size_t)b * Nn + 0) * Gg;
        encIF = pack2(ea[j], ea[128 + j]);
        encGO = pack2(ea[256 + j], ea[384 + j]);
    } else {
#pragma unroll
        for (int k = 0; k < 16; k++) {
            wIF[k]      = pack2(0.5f * Wih1[j * 16 + k],  0.5f * Wih1[(128 + j) * 16 + k]);
            wGO[k]      = pack2(Wih1[(256 + j) * 16 + k], 0.5f * Wih1[(384 + j) * 16 + k]);
            wIF[16 + k] = pack2(0.5f * Whh1[j * 16 + k],  0.5f * Whh1[(128 + j) * 16 + k]);
            wGO[16 + k] = pack2(Whh1[(256 + j) * 16 + k], 0.5f * Whh1[(384 + j) * 16 + k]);
        }
#pragma unroll
        for (int m = 0; m < 8; m++)
            whrp[m] = pack2(Whr1[o_r1 * 128 + 2 * (sub + 8 * m)],
                            Whr1[o_r1 * 128 + 2 * (sub + 8 * m) + 1]);
        bIF = pack2(0.5f * (bih1[j] + bhh1[j]),
                    0.5f * (bih1[128 + j] + bhh1[128 + j]));
        bGO = pack2(bih1[256 + j] + bhh1[256 + j],
                    0.5f * (bih1[384 + j] + bhh1[384 + j]));
        cst = c0v[128 + j];
        optr = (unsigned)b * (FUTc * Nn * Oo) + o_r1;
        if (sub == 0) {
            nm_cur = g_nm[((size_t)b * Nn + 0) * Oo + o_r1];
            const float lp = s0v[o_r1] + nm_cur;
            s_x0[o_r1] = pack2(lp, lp);
            const float h1i = h0v[o_r1];      s_x0[16 + o_r1] = pack2(h1i, h1i);
            const float h2i = h0v[16 + o_r1]; s_x1[16 + o_r1] = pack2(h2i, h2i);
        }
    }
    __syncthreads();

    // prologue: role0 initial carried h1-half (from h0)
    if (role0) {
        u64 a0 = 0, a1 = 0, g0 = 0, g1 = 0;
#pragma unroll
        for (int k = 16; k < 32; k += 2) {
            const u64 xe = s_x0[k], xo = s_x0[k + 1];
            ffma2(a0, xe, wIF[k]); ffma2(a1, xo, wIF[k + 1]);
            ffma2(g0, xe, wGO[k]); ffma2(g1, xo, wGO[k + 1]);
        }
        cIF = add2(a0, a1); cGO = add2(g0, g1);
    }
    __syncthreads();

    // pre-arrive so role0's in-loop bar.sync 4 is unconditional
    if (!role0) asm volatile("bar.arrive 4, 256;" ::: "memory");

#pragma unroll 1
    for (int n = 0; n < Nn; n++) {
        // reps 0..7: plain, branch-free core
#pragma unroll 1
        for (int rep8 = 0; rep8 < 8; rep8++) {
            STEP_CORE(false, false)
        }
        STEP_CORE(true,  false)   // rep 8: prefetch next node
        STEP_CORE(false, false)   // rep 9
        STEP_CORE(false, false)   // rep 10
        STEP_CORE(false, true)    // rep 11: consume prefetch, swap nm
        optr -= (FUTc * Nn * Oo) - Oo;   // advance to next node column
    }
}

extern "C" void kernel_launch(void* const* d_in, const int* in_sizes, int n_in,
                              void* d_out, int out_size) {
    const float* enc  = (const float*)d_in[0];
    const float* mean = (const float*)d_in[1];
    const float* s    = (const float*)d_in[2];
    const float* h0   = (const float*)d_in[3];
    const float* c0   = (const float*)d_in[4];
    const float* Wih0 = (const float*)d_in[5];
    const float* Whh0 = (const float*)d_in[6];
    const float* bih0 = (const float*)d_in[7];
    const float* bhh0 = (const float*)d_in[8];
    const float* Whr0 = (const float*)d_in[9];
    const float* Wih1 = (const float*)d_in[10];
    const float* Whh1 = (const float*)d_in[11];
    const float* bih1 = (const float*)d_in[12];
    const float* bhh1 = (const float*)d_in[13];
    const float* Whr1 = (const float*)d_in[14];
    float* out = (float*)d_out;

    enc_precompute<<<(Bb * Nn) / 32, 256>>>(enc, Wih0, bih0, bhh0);
    nm_precompute<<<(Bb * Nn * Oo + 255) / 256, 256>>>(mean);
    decoder_main<<<Bb, 256>>>(s, h0, c0, Wih0, Whh0, Whr0,
                              Wih1, Whh1, bih1, bhh1, Whr1, out);
}